// round 13
// baseline (speedup 1.0000x reference)
#include <cuda_runtime.h>
#include <cstdint>

#define NN 100000
#define NE 1600000
#define NF 128
#define HD 64

#define NB_N ((NN + 255) / 256)   // 391
#define NB_E ((NE + 255) / 256)   // 6250

// ---------------- scratch (no allocs allowed) ----------------
__device__ __align__(16) float g_dinv[NN];
__device__ __align__(16) float g_t  [NN * HD];   // (h @ W) * dinv[row]
__device__ __align__(16) float g_h  [NN * HD];   // layer output
__device__ __align__(16) int g_deg[NN];
__device__ __align__(16) int g_cursor[NN];
__device__ __align__(16) int g_rowstart[NN + 1];
__device__ __align__(16) int g_csr[NE];
__device__ float g_loss;
__device__ int   g_lsum;

// ---------------- 1: fused init (nodes) + count (edges) ----------------
__global__ void k_ic(const int* __restrict__ labels, const int* __restrict__ ei) {
    int bid = blockIdx.x;
    if (bid < NB_N) {
        int i = bid * 256 + threadIdx.x;
        if (i == 0) { g_loss = 0.f; g_lsum = 0; }
        int v = 0;
        if (i < NN) { g_deg[i] = 0; v = labels[i]; }
        #pragma unroll
        for (int off = 16; off; off >>= 1) v += __shfl_down_sync(0xffffffffu, v, off);
        if ((threadIdx.x & 31) == 0 && v) atomicAdd(&g_lsum, v);
    } else {
        int e = (bid - NB_N) * 256 + threadIdx.x;
        if (e < NE) {
            unsigned c = (unsigned)ei[NE + e];
            if (c < NN) atomicAdd(&g_deg[c], 1);
        }
    }
}

// ---------------- 2: 1-block scan -> rowstart, cursor, dinv ----------------
__global__ void k_scan() {
    const int T = 1024;
    const int CH = (NN + T - 1) / T;
    __shared__ int sh[T];
    int tid = threadIdx.x;
    int lo = tid * CH, hi = lo + CH; if (hi > NN) hi = NN;
    int s = 0;
    for (int i = lo; i < hi; i++) s += g_deg[i];
    sh[tid] = s;
    __syncthreads();
    for (int off = 1; off < T; off <<= 1) {
        int v = (tid >= off) ? sh[tid - off] : 0;
        __syncthreads();
        sh[tid] += v;
        __syncthreads();
    }
    int run = sh[tid] - s;
    for (int i = lo; i < hi; i++) {
        int d = g_deg[i];
        g_rowstart[i] = run;
        g_cursor[i]   = run;
        g_dinv[i]     = rsqrtf((float)(d + 1));
        run += d;
    }
    if (tid == T - 1) g_rowstart[NN] = run;
}

// ---------------- GEMM: t[i,:] = (hin[i,:] @ W) * dinv[i] ----------------
// block 256 = 32 col-pairs x 8 row-threads (4 rows each); tile = 32 rows.
template <int K, bool USEG>
__global__ void __launch_bounds__(256) k_gemm(const float* __restrict__ hin,
                                              const float* __restrict__ W) {
    __shared__ __align__(16) float  sW[K * HD];
    __shared__ __align__(16) float4 srow[32][K / 4];
    const float* src = USEG ? g_h : hin;
    int tid = threadIdx.x;
    for (int j = tid; j < K * HD / 4; j += 256)
        ((float4*)sW)[j] = ((const float4*)W)[j];

    int c2 = tid & 31;
    int rt = tid >> 5;

    for (int rb = blockIdx.x * 32; rb < NN; rb += gridDim.x * 32) {
        __syncthreads();
        for (int j = tid; j < 32 * (K / 4); j += 256) {
            int r = j / (K / 4), kk = j % (K / 4);
            srow[r][kk] = ((const float4*)(src + (size_t)(rb + r) * K))[kk];
        }
        __syncthreads();

        float acc0[4], acc1[4];
        #pragma unroll
        for (int rr = 0; rr < 4; rr++) { acc0[rr] = 0.f; acc1[rr] = 0.f; }

        #pragma unroll
        for (int k4 = 0; k4 < K / 4; k4++) {
            float2 wa = *(const float2*)&sW[(4 * k4 + 0) * HD + 2 * c2];
            float2 wb = *(const float2*)&sW[(4 * k4 + 1) * HD + 2 * c2];
            float2 wc = *(const float2*)&sW[(4 * k4 + 2) * HD + 2 * c2];
            float2 wd = *(const float2*)&sW[(4 * k4 + 3) * HD + 2 * c2];
            #pragma unroll
            for (int rr = 0; rr < 4; rr++) {
                float4 h = srow[rt * 4 + rr][k4];
                acc0[rr] = fmaf(h.x, wa.x, acc0[rr]);
                acc0[rr] = fmaf(h.y, wb.x, acc0[rr]);
                acc0[rr] = fmaf(h.z, wc.x, acc0[rr]);
                acc0[rr] = fmaf(h.w, wd.x, acc0[rr]);
                acc1[rr] = fmaf(h.x, wa.y, acc1[rr]);
                acc1[rr] = fmaf(h.y, wb.y, acc1[rr]);
                acc1[rr] = fmaf(h.z, wc.y, acc1[rr]);
                acc1[rr] = fmaf(h.w, wd.y, acc1[rr]);
            }
        }
        #pragma unroll
        for (int rr = 0; rr < 4; rr++) {
            int gr = rb + rt * 4 + rr;
            float d = g_dinv[gr];
            float2 o = make_float2(acc0[rr] * d, acc1[rr] * d);
            *(float2*)&g_t[(size_t)gr * HD + 2 * c2] = o;
        }
    }
}

// ---------------- fill CSR ----------------
__global__ void k_fill(const int* __restrict__ ei) {
    int e = blockIdx.x * blockDim.x + threadIdx.x;
    if (e >= NE) return;
    unsigned src = (unsigned)ei[e];
    unsigned dst = (unsigned)ei[NE + e];
    if (src >= NN || dst >= NN) return;
    int pos = atomicAdd(&g_cursor[dst], 1);
    g_csr[pos] = (int)src;
}

// ---------------- agg + combine: h = relu(dinv[c]*(t[c]+sum t[src]) + b) ----
// 16 threads per node; unroll-8 (2x int4 index loads), FOUR accumulator chains
__global__ void k_agg(const float* __restrict__ b) {
    int tid  = threadIdx.x;
    int node = blockIdx.x * 16 + (tid >> 4);   // NN % 16 == 0
    int part = tid & 15;

    const float4* __restrict__ t4 = (const float4*)g_t;
    int s = g_rowstart[node];
    int e = g_rowstart[node + 1];

    float4 a0 = t4[(size_t)node * 16 + part];   // self loop
    float4 a1 = make_float4(0.f, 0.f, 0.f, 0.f);
    float4 a2 = make_float4(0.f, 0.f, 0.f, 0.f);
    float4 a3 = make_float4(0.f, 0.f, 0.f, 0.f);

    int i = s;
    int ahead = (s + 3) & ~3;                   // align to int4 boundary
    if (ahead > e) ahead = e;
    for (; i < ahead; i++) {
        float4 v = t4[(size_t)g_csr[i] * 16 + part];
        a0.x += v.x; a0.y += v.y; a0.z += v.z; a0.w += v.w;
    }
    for (; i + 8 <= e; i += 8) {
        int4 ia = *(const int4*)&g_csr[i];
        int4 ib = *(const int4*)&g_csr[i + 4];
        float4 v0 = t4[(size_t)ia.x * 16 + part];
        float4 v1 = t4[(size_t)ia.y * 16 + part];
        float4 v2 = t4[(size_t)ia.z * 16 + part];
        float4 v3 = t4[(size_t)ia.w * 16 + part];
        float4 v4 = t4[(size_t)ib.x * 16 + part];
        float4 v5 = t4[(size_t)ib.y * 16 + part];
        float4 v6 = t4[(size_t)ib.z * 16 + part];
        float4 v7 = t4[(size_t)ib.w * 16 + part];
        a0.x += v0.x; a0.y += v0.y; a0.z += v0.z; a0.w += v0.w;
        a1.x += v1.x; a1.y += v1.y; a1.z += v1.z; a1.w += v1.w;
        a2.x += v2.x; a2.y += v2.y; a2.z += v2.z; a2.w += v2.w;
        a3.x += v3.x; a3.y += v3.y; a3.z += v3.z; a3.w += v3.w;
        a0.x += v4.x; a0.y += v4.y; a0.z += v4.z; a0.w += v4.w;
        a1.x += v5.x; a1.y += v5.y; a1.z += v5.z; a1.w += v5.w;
        a2.x += v6.x; a2.y += v6.y; a2.z += v6.z; a2.w += v6.w;
        a3.x += v7.x; a3.y += v7.y; a3.z += v7.z; a3.w += v7.w;
    }
    if (i + 4 <= e) {
        int4 ia = *(const int4*)&g_csr[i];
        float4 v0 = t4[(size_t)ia.x * 16 + part];
        float4 v1 = t4[(size_t)ia.y * 16 + part];
        float4 v2 = t4[(size_t)ia.z * 16 + part];
        float4 v3 = t4[(size_t)ia.w * 16 + part];
        a0.x += v0.x; a0.y += v0.y; a0.z += v0.z; a0.w += v0.w;
        a1.x += v1.x; a1.y += v1.y; a1.z += v1.z; a1.w += v1.w;
        a2.x += v2.x; a2.y += v2.y; a2.z += v2.z; a2.w += v2.w;
        a3.x += v3.x; a3.y += v3.y; a3.z += v3.z; a3.w += v3.w;
        i += 4;
    }
    for (; i < e; i++) {
        float4 v = t4[(size_t)g_csr[i] * 16 + part];
        a0.x += v.x; a0.y += v.y; a0.z += v.z; a0.w += v.w;
    }
    float4 acc;
    acc.x = (a0.x + a1.x) + (a2.x + a3.x);
    acc.y = (a0.y + a1.y) + (a2.y + a3.y);
    acc.z = (a0.z + a1.z) + (a2.z + a3.z);
    acc.w = (a0.w + a1.w) + (a2.w + a3.w);

    float d = g_dinv[node];
    float4 bb = *(const float4*)&b[part * 4];
    float4 o;
    o.x = fmaxf(fmaf(d, acc.x, bb.x), 0.f);
    o.y = fmaxf(fmaf(d, acc.y, bb.y), 0.f);
    o.z = fmaxf(fmaf(d, acc.z, bb.z), 0.f);
    o.w = fmaxf(fmaf(d, acc.w, bb.w), 0.f);
    ((float4*)g_h)[(size_t)node * 16 + part] = o;
}

// ---------------- MLP head + p output + weighted-BCE ----------------
__global__ void k_head(const float* __restrict__ lW1, const float* __restrict__ lb1,
                       const float* __restrict__ lW2, const float* __restrict__ lb2,
                       const int* __restrict__ labels, float* __restrict__ out_p) {
    __shared__ float sW1[HD * 8];
    __shared__ float sb1[8];
    __shared__ float sW2[8];
    __shared__ float swsum[8];
    int tid = threadIdx.x;
    for (int j = tid; j < HD * 8; j += 256) sW1[j] = lW1[j];
    if (tid < 8) { sb1[tid] = lb1[tid]; sW2[tid] = lW2[tid]; }
    __syncthreads();

    int i = blockIdx.x * 256 + tid;
    float term = 0.f;
    if (i < NN) {
        float z[8];
        #pragma unroll
        for (int o = 0; o < 8; o++) z[o] = sb1[o];
        const float* hr = &g_h[(size_t)i * HD];
        #pragma unroll
        for (int j4 = 0; j4 < HD; j4 += 4) {
            float4 hv = *(const float4*)&hr[j4];
            #pragma unroll
            for (int o = 0; o < 8; o++) {
                z[o] = fmaf(hv.x, sW1[(j4 + 0) * 8 + o], z[o]);
                z[o] = fmaf(hv.y, sW1[(j4 + 1) * 8 + o], z[o]);
                z[o] = fmaf(hv.z, sW1[(j4 + 2) * 8 + o], z[o]);
                z[o] = fmaf(hv.w, sW1[(j4 + 3) * 8 + o], z[o]);
            }
        }
        float z2 = lb2[0];
        #pragma unroll
        for (int o = 0; o < 8; o++) z2 += fmaxf(z[o], 0.f) * sW2[o];
        float p = 1.f / (1.f + expf(-z2));
        out_p[i] = p;

        float pm = (float)g_lsum * (1.0f / NN);
        float y = (float)labels[i];
        float w = y * (1.f - pm) + (1.f - y) * pm;
        float pc = fminf(fmaxf(p, 1e-7f), 1.f - 1e-7f);
        float bce = -(y * logf(pc) + (1.f - y) * logf(1.f - pc));
        term = w * bce;
    }
    #pragma unroll
    for (int off = 16; off; off >>= 1) term += __shfl_down_sync(0xffffffffu, term, off);
    if ((tid & 31) == 0) swsum[tid >> 5] = term;
    __syncthreads();
    if (tid == 0) {
        float s = 0.f;
        #pragma unroll
        for (int k2 = 0; k2 < 8; k2++) s += swsum[k2];
        atomicAdd(&g_loss, s);
    }
}

__global__ void k_final(float* __restrict__ out) {
    out[0] = g_loss * (1.0f / NN);
}

// ---------------- launch ----------------
extern "C" void kernel_launch(void* const* d_in, const int* in_sizes, int n_in,
                              void* d_out, int out_size) {
    const float* x      = (const float*)d_in[0];
    const int*   ei     = (const int*)d_in[1];
    const int*   labels = (const int*)d_in[2];
    const float* W1  = (const float*)d_in[3];
    const float* b1  = (const float*)d_in[4];
    const float* W2  = (const float*)d_in[5];
    const float* b2  = (const float*)d_in[6];
    const float* W3  = (const float*)d_in[7];
    const float* b3  = (const float*)d_in[8];
    const float* lW1 = (const float*)d_in[9];
    const float* lb1 = (const float*)d_in[10];
    const float* lW2 = (const float*)d_in[11];
    const float* lb2 = (const float*)d_in[12];

    float* out = (float*)d_out;
    int loss_elems = out_size - NN;
    float* out_p = out + (loss_elems > 0 ? loss_elems : 0);

    const int TPB = 256;
    const int agg_blocks   = NN / 16;   // 6250
    const int gemm1_blocks = 592;       // grid-stride (48KB smem)
    const int gemm2_blocks = NN / 32;   // 3125, one tile per block (24KB smem)

    k_ic   <<<NB_N + NB_E, TPB>>>(labels, ei);              // 1
    k_scan <<<1, 1024>>>();                                 // 2
    k_gemm<NF, false><<<gemm1_blocks, TPB>>>(x, W1);        // 3
    k_fill <<<NB_E, TPB>>>(ei);                             // 4  <- profiled
    k_agg<<<agg_blocks, TPB>>>(b1);                         // 5

    k_gemm<HD, true><<<gemm2_blocks, TPB>>>(nullptr, W2);   // 6
    k_agg<<<agg_blocks, TPB>>>(b2);                         // 7

    k_gemm<HD, true><<<gemm2_blocks, TPB>>>(nullptr, W3);   // 8
    k_agg<<<agg_blocks, TPB>>>(b3);                         // 9

    k_head<<<NB_N, TPB>>>(lW1, lb1, lW2, lb2, labels, out_p);  // 10
    if (loss_elems > 0) k_final<<<1, 1>>>(out);             // 11
}

// round 14
// speedup vs baseline: 1.0832x; 1.0832x over previous
#include <cuda_runtime.h>
#include <cstdint>

#define NN 100000
#define NE 1600000
#define NF 128
#define HD 64

#define NB_N ((NN + 255) / 256)   // 391
#define NB_E ((NE + 255) / 256)   // 6250
#define GEMM1_BLOCKS 592

// ---------------- scratch (no allocs allowed) ----------------
__device__ __align__(16) float g_dinv[NN];
__device__ __align__(16) float g_t  [NN * HD];   // (h @ W) * dinv[row]
__device__ __align__(16) float g_h  [NN * HD];   // layer output
__device__ __align__(16) int g_deg[NN];
__device__ __align__(16) int g_cursor[NN];
__device__ __align__(16) int g_rowstart[NN + 1];
__device__ __align__(16) int g_csr[NE];
__device__ float g_loss;
__device__ int   g_lsum;

// ---------------- 1: fused init (nodes) + count (edges) ----------------
__global__ void k_ic(const int* __restrict__ labels, const int* __restrict__ ei) {
    int bid = blockIdx.x;
    if (bid < NB_N) {
        int i = bid * 256 + threadIdx.x;
        if (i == 0) { g_loss = 0.f; g_lsum = 0; }
        int v = 0;
        if (i < NN) { g_deg[i] = 0; v = labels[i]; }
        #pragma unroll
        for (int off = 16; off; off >>= 1) v += __shfl_down_sync(0xffffffffu, v, off);
        if ((threadIdx.x & 31) == 0 && v) atomicAdd(&g_lsum, v);
    } else {
        int e = (bid - NB_N) * 256 + threadIdx.x;
        if (e < NE) {
            unsigned c = (unsigned)ei[NE + e];
            if (c < NN) atomicAdd(&g_deg[c], 1);
        }
    }
}

// ---------------- 2: 1-block scan -> rowstart, cursor, dinv ----------------
__global__ void k_scan() {
    const int T = 1024;
    const int CH = (NN + T - 1) / T;
    __shared__ int sh[T];
    int tid = threadIdx.x;
    int lo = tid * CH, hi = lo + CH; if (hi > NN) hi = NN;
    int s = 0;
    for (int i = lo; i < hi; i++) s += g_deg[i];
    sh[tid] = s;
    __syncthreads();
    for (int off = 1; off < T; off <<= 1) {
        int v = (tid >= off) ? sh[tid - off] : 0;
        __syncthreads();
        sh[tid] += v;
        __syncthreads();
    }
    int run = sh[tid] - s;
    for (int i = lo; i < hi; i++) {
        int d = g_deg[i];
        g_rowstart[i] = run;
        g_cursor[i]   = run;
        g_dinv[i]     = rsqrtf((float)(d + 1));
        run += d;
    }
    if (tid == T - 1) g_rowstart[NN] = run;
}

// ---------------- gemm body (R10-proven retile) ----------------
template <int K, bool USEG>
__device__ __forceinline__ void gemm_body(const float* __restrict__ hin,
                                          const float* __restrict__ W,
                                          float* sW, float4 (*srow)[K / 4],
                                          int bid, int nblocks) {
    const float* src = USEG ? g_h : hin;
    int tid = threadIdx.x;
    for (int j = tid; j < K * HD / 4; j += 256)
        ((float4*)sW)[j] = ((const float4*)W)[j];

    int c2 = tid & 31;
    int rt = tid >> 5;

    for (int rb = bid * 32; rb < NN; rb += nblocks * 32) {
        __syncthreads();
        for (int j = tid; j < 32 * (K / 4); j += 256) {
            int r = j / (K / 4), kk = j % (K / 4);
            srow[r][kk] = ((const float4*)(src + (size_t)(rb + r) * K))[kk];
        }
        __syncthreads();

        float acc0[4], acc1[4];
        #pragma unroll
        for (int rr = 0; rr < 4; rr++) { acc0[rr] = 0.f; acc1[rr] = 0.f; }

        #pragma unroll
        for (int k4 = 0; k4 < K / 4; k4++) {
            float2 wa = *(const float2*)&sW[(4 * k4 + 0) * HD + 2 * c2];
            float2 wb = *(const float2*)&sW[(4 * k4 + 1) * HD + 2 * c2];
            float2 wc = *(const float2*)&sW[(4 * k4 + 2) * HD + 2 * c2];
            float2 wd = *(const float2*)&sW[(4 * k4 + 3) * HD + 2 * c2];
            #pragma unroll
            for (int rr = 0; rr < 4; rr++) {
                float4 h = srow[rt * 4 + rr][k4];
                acc0[rr] = fmaf(h.x, wa.x, acc0[rr]);
                acc0[rr] = fmaf(h.y, wb.x, acc0[rr]);
                acc0[rr] = fmaf(h.z, wc.x, acc0[rr]);
                acc0[rr] = fmaf(h.w, wd.x, acc0[rr]);
                acc1[rr] = fmaf(h.x, wa.y, acc1[rr]);
                acc1[rr] = fmaf(h.y, wb.y, acc1[rr]);
                acc1[rr] = fmaf(h.z, wc.y, acc1[rr]);
                acc1[rr] = fmaf(h.w, wd.y, acc1[rr]);
            }
        }
        #pragma unroll
        for (int rr = 0; rr < 4; rr++) {
            int gr = rb + rt * 4 + rr;
            float d = g_dinv[gr];
            float2 o = make_float2(acc0[rr] * d, acc1[rr] * d);
            *(float2*)&g_t[(size_t)gr * HD + 2 * c2] = o;
        }
    }
}

// ---------------- 3: fused [gemm1 || fill] (both depend only on scan) ------
__global__ void __launch_bounds__(256) k_gemmfill(const float* __restrict__ x,
                                                  const float* __restrict__ W1,
                                                  const int* __restrict__ ei) {
    __shared__ __align__(16) float  sW[NF * HD];        // 32KB
    __shared__ __align__(16) float4 srow[32][NF / 4];   // 16KB
    int bid = blockIdx.x;
    if (bid >= GEMM1_BLOCKS) {
        int e = (bid - GEMM1_BLOCKS) * 256 + threadIdx.x;
        if (e < NE) {
            unsigned src = (unsigned)ei[e];
            unsigned dst = (unsigned)ei[NE + e];
            if (src < NN && dst < NN) {
                int pos = atomicAdd(&g_cursor[dst], 1);
                g_csr[pos] = (int)src;
            }
        }
        return;
    }
    gemm_body<NF, false>(x, W1, sW, srow, bid, GEMM1_BLOCKS);
}

// ---------------- gemm2/3 standalone ----------------
template <int K, bool USEG>
__global__ void __launch_bounds__(256) k_gemm(const float* __restrict__ hin,
                                              const float* __restrict__ W) {
    __shared__ __align__(16) float  sW[K * HD];
    __shared__ __align__(16) float4 srow[32][K / 4];
    gemm_body<K, USEG>(hin, W, sW, srow, blockIdx.x, gridDim.x);
}

// ---------------- agg + combine: h = relu(dinv[c]*(t[c]+sum t[src]) + b) ----
// 16 threads per node; unroll-4 two chains; capped regs for high occupancy
__global__ void __launch_bounds__(256, 6) k_agg(const float* __restrict__ b) {
    int tid  = threadIdx.x;
    int node = blockIdx.x * 16 + (tid >> 4);   // NN % 16 == 0
    int part = tid & 15;

    const float4* __restrict__ t4 = (const float4*)g_t;
    int s = g_rowstart[node];
    int e = g_rowstart[node + 1];

    float4 a0 = t4[(size_t)node * 16 + part];   // self loop
    float4 a1 = make_float4(0.f, 0.f, 0.f, 0.f);
    int i = s;
    for (; i + 4 <= e; i += 4) {
        int s0 = g_csr[i],     s1 = g_csr[i + 1];
        int s2 = g_csr[i + 2], s3 = g_csr[i + 3];
        float4 v0 = t4[(size_t)s0 * 16 + part];
        float4 v1 = t4[(size_t)s1 * 16 + part];
        float4 v2 = t4[(size_t)s2 * 16 + part];
        float4 v3 = t4[(size_t)s3 * 16 + part];
        a0.x += v0.x; a0.y += v0.y; a0.z += v0.z; a0.w += v0.w;
        a1.x += v1.x; a1.y += v1.y; a1.z += v1.z; a1.w += v1.w;
        a0.x += v2.x; a0.y += v2.y; a0.z += v2.z; a0.w += v2.w;
        a1.x += v3.x; a1.y += v3.y; a1.z += v3.z; a1.w += v3.w;
    }
    for (; i < e; i++) {
        float4 v = t4[(size_t)g_csr[i] * 16 + part];
        a0.x += v.x; a0.y += v.y; a0.z += v.z; a0.w += v.w;
    }
    float4 acc = make_float4(a0.x + a1.x, a0.y + a1.y, a0.z + a1.z, a0.w + a1.w);

    float d = g_dinv[node];
    float4 bb = *(const float4*)&b[part * 4];
    float4 o;
    o.x = fmaxf(fmaf(d, acc.x, bb.x), 0.f);
    o.y = fmaxf(fmaf(d, acc.y, bb.y), 0.f);
    o.z = fmaxf(fmaf(d, acc.z, bb.z), 0.f);
    o.w = fmaxf(fmaf(d, acc.w, bb.w), 0.f);
    ((float4*)g_h)[(size_t)node * 16 + part] = o;
}

// ---------------- MLP head + p output + weighted-BCE ----------------
__global__ void k_head(const float* __restrict__ lW1, const float* __restrict__ lb1,
                       const float* __restrict__ lW2, const float* __restrict__ lb2,
                       const int* __restrict__ labels, float* __restrict__ out_p) {
    __shared__ float sW1[HD * 8];
    __shared__ float sb1[8];
    __shared__ float sW2[8];
    __shared__ float swsum[8];
    int tid = threadIdx.x;
    for (int j = tid; j < HD * 8; j += 256) sW1[j] = lW1[j];
    if (tid < 8) { sb1[tid] = lb1[tid]; sW2[tid] = lW2[tid]; }
    __syncthreads();

    int i = blockIdx.x * 256 + tid;
    float term = 0.f;
    if (i < NN) {
        float z[8];
        #pragma unroll
        for (int o = 0; o < 8; o++) z[o] = sb1[o];
        const float* hr = &g_h[(size_t)i * HD];
        #pragma unroll
        for (int j4 = 0; j4 < HD; j4 += 4) {
            float4 hv = *(const float4*)&hr[j4];
            #pragma unroll
            for (int o = 0; o < 8; o++) {
                z[o] = fmaf(hv.x, sW1[(j4 + 0) * 8 + o], z[o]);
                z[o] = fmaf(hv.y, sW1[(j4 + 1) * 8 + o], z[o]);
                z[o] = fmaf(hv.z, sW1[(j4 + 2) * 8 + o], z[o]);
                z[o] = fmaf(hv.w, sW1[(j4 + 3) * 8 + o], z[o]);
            }
        }
        float z2 = lb2[0];
        #pragma unroll
        for (int o = 0; o < 8; o++) z2 += fmaxf(z[o], 0.f) * sW2[o];
        float p = 1.f / (1.f + expf(-z2));
        out_p[i] = p;

        float pm = (float)g_lsum * (1.0f / NN);
        float y = (float)labels[i];
        float w = y * (1.f - pm) + (1.f - y) * pm;
        float pc = fminf(fmaxf(p, 1e-7f), 1.f - 1e-7f);
        float bce = -(y * logf(pc) + (1.f - y) * logf(1.f - pc));
        term = w * bce;
    }
    #pragma unroll
    for (int off = 16; off; off >>= 1) term += __shfl_down_sync(0xffffffffu, term, off);
    if ((tid & 31) == 0) swsum[tid >> 5] = term;
    __syncthreads();
    if (tid == 0) {
        float s = 0.f;
        #pragma unroll
        for (int k2 = 0; k2 < 8; k2++) s += swsum[k2];
        atomicAdd(&g_loss, s);
    }
}

__global__ void k_final(float* __restrict__ out) {
    out[0] = g_loss * (1.0f / NN);
}

// ---------------- launch ----------------
extern "C" void kernel_launch(void* const* d_in, const int* in_sizes, int n_in,
                              void* d_out, int out_size) {
    const float* x      = (const float*)d_in[0];
    const int*   ei     = (const int*)d_in[1];
    const int*   labels = (const int*)d_in[2];
    const float* W1  = (const float*)d_in[3];
    const float* b1  = (const float*)d_in[4];
    const float* W2  = (const float*)d_in[5];
    const float* b2  = (const float*)d_in[6];
    const float* W3  = (const float*)d_in[7];
    const float* b3  = (const float*)d_in[8];
    const float* lW1 = (const float*)d_in[9];
    const float* lb1 = (const float*)d_in[10];
    const float* lW2 = (const float*)d_in[11];
    const float* lb2 = (const float*)d_in[12];

    float* out = (float*)d_out;
    int loss_elems = out_size - NN;
    float* out_p = out + (loss_elems > 0 ? loss_elems : 0);

    const int TPB = 256;
    const int agg_blocks   = NN / 16;   // 6250
    const int gemm2_blocks = NN / 32;   // 3125

    k_ic   <<<NB_N + NB_E, TPB>>>(labels, ei);                    // 1
    k_scan <<<1, 1024>>>();                                       // 2
    k_gemmfill<<<GEMM1_BLOCKS + NB_E, TPB>>>(x, W1, ei);          // 3
    k_agg<<<agg_blocks, TPB>>>(b1);                               // 4  <- profiled
    k_gemm<HD, true><<<gemm2_blocks, TPB>>>(nullptr, W2);         // 5
    k_agg<<<agg_blocks, TPB>>>(b2);                               // 6
    k_gemm<HD, true><<<gemm2_blocks, TPB>>>(nullptr, W3);         // 7
    k_agg<<<agg_blocks, TPB>>>(b3);                               // 8
    k_head<<<NB_N, TPB>>>(lW1, lb1, lW2, lb2, labels, out_p);     // 9
    if (loss_elems > 0) k_final<<<1, 1>>>(out);                   // 10
}